// round 3
// baseline (speedup 1.0000x reference)
#include <cuda_runtime.h>
#include <cstdint>

// Problem constants
// x: (8, 32, 32, 32, 32) f32   -> d_in[0]
// W: (32, 16, 3, 3, 3)   f32   -> d_in[1]
// b: (16,)               f32   -> d_in[2]
// out: (8, 1, 10, 10, 10) f32  -> d_out (8000 elements)

#define NCELLS      8000     // 8 * 10*10*10
#define NGROUPS     2000     // cells / 4
#define THREADS     256
#define GRID_BLKS   304      // 152 SMs * 2

// smem layout (floats):
//   Ws : [0, 13824)                 W as [ci][k][co]  (ci*432 + k*16 + co)
//   xs : [13824, 13824+8192)        4 cells x [ci][d][h][w] (2048 each)
//   red: [22016, 22016+128)         per-warp cmax[16]
//   bsum at red[128]
#define WS_OFF   0
#define XS_OFF   13824
#define RED_OFF  (13824 + 8192)
#define SMEM_FLOATS (13824 + 8192 + 160)
#define SMEM_BYTES  (SMEM_FLOATS * 4)

__device__ __forceinline__ unsigned long long pack2(float v) {
    unsigned long long r;
    asm("mov.b64 %0, {%1, %1};" : "=l"(r) : "f"(v));
    return r;
}
__device__ __forceinline__ void fma2(unsigned long long& d,
                                     unsigned long long a,
                                     unsigned long long b) {
    asm("fma.rn.f32x2 %0, %1, %2, %0;" : "+l"(d) : "l"(a), "l"(b));
}
__device__ __forceinline__ void unpack2(unsigned long long v, float& lo, float& hi) {
    asm("mov.b64 {%0, %1}, %2;" : "=f"(lo), "=f"(hi) : "l"(v));
}

extern "C" __global__ void __launch_bounds__(THREADS, 2)
fused_ct3d_pool_kernel(const float* __restrict__ x,
                       const float* __restrict__ W,
                       const float* __restrict__ b,
                       float* __restrict__ out)
{
    extern __shared__ float smem[];
    float* Ws  = smem + WS_OFF;
    float* xs  = smem + XS_OFF;
    float* red = smem + RED_OFF;

    const int tid = threadIdx.x;

    // ---- Stage W once per block: global [ci][co][k] -> smem [ci][k][co] ----
    for (int i = tid; i < 13824; i += THREADS) {
        int ci = i / 432;
        int r  = i - ci * 432;
        int co = r / 27;
        int k  = r - co * 27;
        Ws[ci * 432 + k * 16 + co] = W[i];
    }
    if (tid == 0) {
        float s = 0.f;
        #pragma unroll
        for (int i = 0; i < 16; i++) s += b[i];
        red[128] = s;
    }
    __syncthreads();
    const float bsum = red[128];

    const int warp  = tid >> 5;
    const int lane  = tid & 31;
    const int cellj = warp >> 1;   // 0..3 : cell within group
    const int role  = warp & 1;    // 0 = list A {ooo,4,2}, 1 = list B
    float* xc = xs + cellj * 2048;

    // lane -> position within a 3x3x3 parity class (lanes 27..31 duplicate 26)
    const int q  = (lane < 27) ? lane : 26;
    const int a  = q / 9;
    const int bq = (q - a * 9) / 3;
    const int c  = q - a * 9 - bq * 3;

    for (int cg = blockIdx.x; cg < NGROUPS; cg += gridDim.x) {
        const int cell = cg * 4 + cellj;
        const int n  = cell / 1000;
        const int r3 = cell - n * 1000;
        const int pz = r3 / 100;
        const int py = (r3 / 10) % 10;
        const int px = r3 % 10;
        const int bd = 3 * pz, bh = 3 * py, bw = 3 * px;

        __syncthreads();   // previous iteration fully consumed xs/red

        // ---- Stage 4x4x4x32 input window for this cell (64 threads/pair) ----
        {
            const int lt = tid & 63;
            const float* xn = x + (size_t)n * 32 * 32768;
            for (int row = lt; row < 512; row += 64) {
                int ci = row >> 4;
                int d  = (row >> 2) & 3;
                int h  = row & 3;
                const float* src = xn + ci * 32768 + (bd + d) * 1024 + (bh + h) * 32 + bw;
                float* dst = xc + ci * 64 + d * 16 + h * 4;
                dst[0] = src[0]; dst[1] = src[1]; dst[2] = src[2]; dst[3] = src[3];
            }
        }
        __syncthreads();

        // ---- Compute: warp processes its parity classes ----
        float cmax[16];
        #pragma unroll
        for (int i = 0; i < 16; i++) cmax[i] = -3.402823466e38f;

        const int ncls = role ? 5 : 3;
        #pragma unroll 1
        for (int ic = 0; ic < ncls; ic++) {
            int cls;
            if (role) { const int lb[5] = {6, 5, 4, 2, 0}; cls = lb[ic]; }
            else      { const int la[3] = {7, 3, 1};       cls = la[ic]; }
            const int pd = (cls >> 2) & 1;
            const int ph = (cls >> 1) & 1;
            const int pw = cls & 1;

            unsigned long long acc[8];
            #pragma unroll
            for (int i = 0; i < 8; i++) acc[i] = 0ull;

            const int nd = pd + 1, nh = ph + 1, nw = pw + 1;
            #pragma unroll 1
            for (int td = 0; td < nd; td++) {
                const int kd = pd ? (2 * td)      : 1;
                const int rd = pd ? (a + 1 - td)  : a;
                #pragma unroll 1
                for (int th2 = 0; th2 < nh; th2++) {
                    const int kh = ph ? (2 * th2)     : 1;
                    const int rh = ph ? (bq + 1 - th2) : bq;
                    #pragma unroll 1
                    for (int tw2 = 0; tw2 < nw; tw2++) {
                        const int kw = pw ? (2 * tw2)    : 1;
                        const int rw = pw ? (c + 1 - tw2) : c;
                        const int k  = (kd * 3 + kh) * 3 + kw;
                        const float* xp = xc + rd * 16 + rh * 4 + rw;
                        const ulonglong2* wp =
                            reinterpret_cast<const ulonglong2*>(Ws) + k * 4;
                        #pragma unroll
                        for (int ci = 0; ci < 32; ci++) {
                            unsigned long long xx = pack2(xp[ci * 64]);
                            ulonglong2 w0 = wp[ci * 108 + 0];
                            ulonglong2 w1 = wp[ci * 108 + 1];
                            ulonglong2 w2 = wp[ci * 108 + 2];
                            ulonglong2 w3 = wp[ci * 108 + 3];
                            fma2(acc[0], xx, w0.x); fma2(acc[1], xx, w0.y);
                            fma2(acc[2], xx, w1.x); fma2(acc[3], xx, w1.y);
                            fma2(acc[4], xx, w2.x); fma2(acc[5], xx, w2.y);
                            fma2(acc[6], xx, w3.x); fma2(acc[7], xx, w3.y);
                        }
                    }
                }
            }
            // fold this class's y values into running per-co max
            #pragma unroll
            for (int i = 0; i < 8; i++) {
                float lo, hi;
                unpack2(acc[i], lo, hi);
                cmax[2 * i]     = fmaxf(cmax[2 * i], lo);
                cmax[2 * i + 1] = fmaxf(cmax[2 * i + 1], hi);
            }
        }

        // ---- per-warp butterfly max over positions ----
        #pragma unroll
        for (int i = 0; i < 16; i++) {
            #pragma unroll
            for (int off = 16; off; off >>= 1)
                cmax[i] = fmaxf(cmax[i], __shfl_xor_sync(0xffffffffu, cmax[i], off));
        }
        if (lane == 0) {
            #pragma unroll
            for (int i = 0; i < 16; i++) red[warp * 16 + i] = cmax[i];
        }
        __syncthreads();

        // ---- combine the two warps of each cell, add bias-sum, write out ----
        if (tid < 4) {
            float t = 0.f;
            #pragma unroll
            for (int i = 0; i < 16; i++)
                t += fmaxf(red[(2 * tid) * 16 + i], red[(2 * tid + 1) * 16 + i]);
            out[cg * 4 + tid] = t + bsum;
        }
    }
}

extern "C" void kernel_launch(void* const* d_in, const int* in_sizes, int n_in,
                              void* d_out, int out_size)
{
    const float* x = (const float*)d_in[0];
    const float* W = (const float*)d_in[1];
    const float* b = (const float*)d_in[2];
    float* out = (float*)d_out;

    cudaFuncSetAttribute(fused_ct3d_pool_kernel,
                         cudaFuncAttributeMaxDynamicSharedMemorySize, SMEM_BYTES);
    fused_ct3d_pool_kernel<<<GRID_BLKS, THREADS, SMEM_BYTES>>>(x, W, b, out);
}

// round 8
// speedup vs baseline: 1.2543x; 1.2543x over previous
#include <cuda_runtime.h>
#include <cstdint>

// x: (8, 32, 32, 32, 32) f32   -> d_in[0]
// W: (32, 16, 3, 3, 3)   f32   -> d_in[1]
// b: (16,)               f32   -> d_in[2]
// out: (8, 1, 10, 10, 10) f32  -> d_out (8000 elements)

#define NG16      500         // groups of 16 cells
#define THREADS   512
#define GRID_BLKS 152

// smem layout (floats):
//   Ws : [0, 13824)                 W as [ci][k][co]  (ci*432 + k*16 + co)
//   xs : [13824, +32768)            16 cells x [ci][d*16+h*4+w], ci stride 64
//   red: [46592, +512)              per-warp cmax[32] (16 per cell)
//   ctr broadcast uint at red[512]
#define WS_OFF   0
#define XS_OFF   13824
#define XC_CI    64
#define XC_CELL  (32 * XC_CI)             // 2048
#define RED_OFF  (XS_OFF + 16 * XC_CELL)  // 46592
#define SMEM_FLOATS (RED_OFF + 512 + 8)
#define SMEM_BYTES  (SMEM_FLOATS * 4)

__device__ unsigned g_ctr;

__device__ __forceinline__ unsigned long long pack2(float v) {
    unsigned long long r;
    asm("mov.b64 %0, {%1, %1};" : "=l"(r) : "f"(v));
    return r;
}
__device__ __forceinline__ void fma2(unsigned long long& d,
                                     unsigned long long a,
                                     unsigned long long b) {
    asm("fma.rn.f32x2 %0, %1, %2, %0;" : "+l"(d) : "l"(a), "l"(b));
}
__device__ __forceinline__ void unpack2(unsigned long long v, float& lo, float& hi) {
    asm("mov.b64 {%0, %1}, %2;" : "=f"(lo), "=f"(hi) : "l"(v));
}

extern "C" __global__ void __launch_bounds__(THREADS, 1)
fused_ct3d_pool_kernel(const float* __restrict__ x,
                       const float* __restrict__ W,
                       const float* __restrict__ b,
                       float* __restrict__ out)
{
    extern __shared__ float smem[];
    float* Ws  = smem + WS_OFF;
    float* xs  = smem + XS_OFF;
    float* red = smem + RED_OFF;
    unsigned* ctr_bc = (unsigned*)(red + 512);

    const int tid = threadIdx.x;

    // ---- Stage W once per block: global [ci][co][k] -> smem [ci][k][co] ----
    for (int i = tid; i < 13824; i += THREADS) {
        int ci = i / 432;
        int r  = i - ci * 432;
        int co = r / 27;
        int k  = r - co * 27;
        Ws[ci * 432 + k * 16 + co] = W[i];
    }
    float bsum = 0.f;
    #pragma unroll
    for (int i = 0; i < 16; i++) bsum += b[i];

    const int warp = tid >> 5;      // 0..15
    const int lane = tid & 31;
    const int pair = warp >> 1;     // 0..7 : cell-pair within group of 16
    const int role = warp & 1;      // 0 = {7,3,1} (14 units), 1 = {6,5,4,2,0} (13)

    // lane -> position within a 3x3x3 parity class (lanes 27..31 dup q=26)
    const int q  = (lane < 27) ? lane : 26;
    const int a  = q / 9;
    const int bq = (q - a * 9) / 3;
    const int c  = q - a * 9 - bq * 3;

    float* xc0 = xs + (pair * 2) * XC_CELL;
    float* xc1 = xc0 + XC_CELL;

    while (true) {
        __syncthreads();            // previous iteration fully consumed
        if (tid == 0) *ctr_bc = atomicAdd(&g_ctr, 1u);
        __syncthreads();
        const unsigned g = *ctr_bc;
        if (g >= NG16) break;

        // ---- Stage 16 cells' 4x4x4x32 windows ----
        // iter k handles cell k; thread layout within cell:
        //   ci = tid>>4, d = (tid>>2)&3, h = tid&3  -> float4 row of 4 w's
        {
            const int ci = tid >> 4;
            const int d  = (tid >> 2) & 3;
            const int h  = tid & 3;
            #pragma unroll 1
            for (int cellj = 0; cellj < 16; cellj++) {
                const int cell = g * 16 + cellj;
                const int n  = cell / 1000;
                const int r3 = cell - n * 1000;
                const int pz = r3 / 100;
                const int py = (r3 / 10) % 10;
                const int px = r3 % 10;
                const float* src = x + ((size_t)(n * 32 + ci)) * 32768
                                     + (3 * pz + d) * 1024 + (3 * py + h) * 32 + 3 * px;
                float4 v;
                v.x = src[0]; v.y = src[1]; v.z = src[2]; v.w = src[3];
                float* dst = xs + cellj * XC_CELL + ci * XC_CI + d * 16 + h * 4;
                *reinterpret_cast<float4*>(dst) = v;
            }
        }
        __syncthreads();

        // ---- Compute: warp processes its parity classes for BOTH cells ----
        float cmax0[16], cmax1[16];
        #pragma unroll
        for (int i = 0; i < 16; i++) { cmax0[i] = -3.402823466e38f; cmax1[i] = -3.402823466e38f; }

        const int ncls = role ? 5 : 3;
        #pragma unroll 1
        for (int ic = 0; ic < ncls; ic++) {
            int cls;
            if (role) { const int lb[5] = {6, 5, 4, 2, 0}; cls = lb[ic]; }
            else      { const int la[3] = {7, 3, 1};       cls = la[ic]; }
            const int pd = (cls >> 2) & 1;
            const int ph = (cls >> 1) & 1;
            const int pw = cls & 1;

            unsigned long long acc0[8], acc1[8];
            #pragma unroll
            for (int i = 0; i < 8; i++) { acc0[i] = 0ull; acc1[i] = 0ull; }

            const int nd = pd + 1, nh = ph + 1, nw = pw + 1;
            #pragma unroll 1
            for (int td = 0; td < nd; td++) {
                const int kd = pd ? (2 * td)     : 1;
                const int rd = pd ? (a + 1 - td) : a;
                #pragma unroll 1
                for (int th2 = 0; th2 < nh; th2++) {
                    const int kh = ph ? (2 * th2)      : 1;
                    const int rh = ph ? (bq + 1 - th2) : bq;
                    #pragma unroll 1
                    for (int tw2 = 0; tw2 < nw; tw2++) {
                        const int kw = pw ? (2 * tw2)   : 1;
                        const int rw = pw ? (c + 1 - tw2) : c;
                        const int k  = (kd * 3 + kh) * 3 + kw;
                        const int xoff = rd * 16 + rh * 4 + rw;
                        const float* xp0 = xc0 + xoff;
                        const float* xp1 = xc1 + xoff;
                        const ulonglong2* wp =
                            reinterpret_cast<const ulonglong2*>(Ws) + k * 4;
                        #pragma unroll 4
                        for (int ci = 0; ci < 32; ci++) {
                            unsigned long long xx0 = pack2(xp0[ci * XC_CI]);
                            unsigned long long xx1 = pack2(xp1[ci * XC_CI]);
                            ulonglong2 w0 = wp[ci * 108 + 0];
                            ulonglong2 w1 = wp[ci * 108 + 1];
                            ulonglong2 w2 = wp[ci * 108 + 2];
                            ulonglong2 w3 = wp[ci * 108 + 3];
                            fma2(acc0[0], xx0, w0.x); fma2(acc0[1], xx0, w0.y);
                            fma2(acc0[2], xx0, w1.x); fma2(acc0[3], xx0, w1.y);
                            fma2(acc0[4], xx0, w2.x); fma2(acc0[5], xx0, w2.y);
                            fma2(acc0[6], xx0, w3.x); fma2(acc0[7], xx0, w3.y);
                            fma2(acc1[0], xx1, w0.x); fma2(acc1[1], xx1, w0.y);
                            fma2(acc1[2], xx1, w1.x); fma2(acc1[3], xx1, w1.y);
                            fma2(acc1[4], xx1, w2.x); fma2(acc1[5], xx1, w2.y);
                            fma2(acc1[6], xx1, w3.x); fma2(acc1[7], xx1, w3.y);
                        }
                    }
                }
            }
            #pragma unroll
            for (int i = 0; i < 8; i++) {
                float lo, hi;
                unpack2(acc0[i], lo, hi);
                cmax0[2 * i]     = fmaxf(cmax0[2 * i], lo);
                cmax0[2 * i + 1] = fmaxf(cmax0[2 * i + 1], hi);
                unpack2(acc1[i], lo, hi);
                cmax1[2 * i]     = fmaxf(cmax1[2 * i], lo);
                cmax1[2 * i + 1] = fmaxf(cmax1[2 * i + 1], hi);
            }
        }

        // ---- per-warp butterfly max over positions ----
        #pragma unroll
        for (int i = 0; i < 16; i++) {
            #pragma unroll
            for (int off = 16; off; off >>= 1) {
                cmax0[i] = fmaxf(cmax0[i], __shfl_xor_sync(0xffffffffu, cmax0[i], off));
                cmax1[i] = fmaxf(cmax1[i], __shfl_xor_sync(0xffffffffu, cmax1[i], off));
            }
        }
        if (lane == 0) {
            #pragma unroll
            for (int i = 0; i < 16; i++) {
                red[warp * 32 + i]      = cmax0[i];
                red[warp * 32 + 16 + i] = cmax1[i];
            }
        }
        __syncthreads();

        // ---- combine A/B roles per cell, add bias-sum, write out ----
        if (tid < 16) {
            const int p = tid >> 1;       // pair
            const int s = tid & 1;        // cell within pair
            float t = 0.f;
            #pragma unroll
            for (int i = 0; i < 16; i++)
                t += fmaxf(red[(2 * p) * 32 + s * 16 + i],
                           red[(2 * p + 1) * 32 + s * 16 + i]);
            out[g * 16 + tid] = t + bsum;
        }
    }
}

extern "C" void kernel_launch(void* const* d_in, const int* in_sizes, int n_in,
                              void* d_out, int out_size)
{
    const float* x = (const float*)d_in[0];
    const float* W = (const float*)d_in[1];
    const float* b = (const float*)d_in[2];
    float* out = (float*)d_out;

    void* ctr_addr = nullptr;
    cudaGetSymbolAddress(&ctr_addr, g_ctr);
    cudaMemsetAsync(ctr_addr, 0, sizeof(unsigned));

    cudaFuncSetAttribute(fused_ct3d_pool_kernel,
                         cudaFuncAttributeMaxDynamicSharedMemorySize, SMEM_BYTES);
    fused_ct3d_pool_kernel<<<GRID_BLKS, THREADS, SMEM_BYTES>>>(x, W, b, out);
}

// round 10
// speedup vs baseline: 1.3009x; 1.0372x over previous
#include <cuda_runtime.h>
#include <cstdint>

// x: (8, 32, 32, 32, 32) f32   -> d_in[0]
// W: (32, 16, 3, 3, 3)   f32   -> d_in[1]
// b: (16,)               f32   -> d_in[2]
// out: (8, 1, 10, 10, 10) f32  -> d_out (8000 elements)

#define NG16      500         // groups of 16 cells
#define THREADS   512
#define GRID_BLKS 152

// smem layout (floats):
//   Ws : [0, 13824)                 W as [ci][k][co]  (ci*432 + k*16 + co)
//   xs : [13824, +32768)            4 quads x [ci][pos][cell4] float4;
//                                   float4 index = q*2048 + ci*64 + d*16+h*4+w
//   red: [46592, +512)              per-warp cmax[32] (4 cells x 8 co-half)
//   cb : [47104, +16)               per-cell gmem base offsets (int)
//   ctr broadcast uint after cb
#define WS_OFF   0
#define XS_OFF   13824
#define RED_OFF  (XS_OFF + 32768)        // 46592
#define CB_OFF   (RED_OFF + 512)         // 47104
#define SMEM_FLOATS (CB_OFF + 16 + 8)
#define SMEM_BYTES  (SMEM_FLOATS * 4)

__device__ unsigned g_ctr;

__device__ __forceinline__ unsigned long long pack2(float v) {
    unsigned long long r;
    asm("mov.b64 %0, {%1, %1};" : "=l"(r) : "f"(v));
    return r;
}
__device__ __forceinline__ void fma2(unsigned long long& d,
                                     unsigned long long a,
                                     unsigned long long b) {
    asm("fma.rn.f32x2 %0, %1, %2, %0;" : "+l"(d) : "l"(a), "l"(b));
}
__device__ __forceinline__ void unpack2(unsigned long long v, float& lo, float& hi) {
    asm("mov.b64 {%0, %1}, %2;" : "=f"(lo), "=f"(hi) : "l"(v));
}

extern "C" __global__ void __launch_bounds__(THREADS, 1)
fused_ct3d_pool_kernel(const float* __restrict__ x,
                       const float* __restrict__ W,
                       const float* __restrict__ b,
                       float* __restrict__ out)
{
    extern __shared__ float smem[];
    float*  Ws  = smem + WS_OFF;
    float4* xs4 = reinterpret_cast<float4*>(smem + XS_OFF);
    float*  red = smem + RED_OFF;
    int*    cb  = (int*)(smem + CB_OFF);
    unsigned* ctr_bc = (unsigned*)(smem + CB_OFF + 16);

    const int tid = threadIdx.x;

    // ---- Stage W once per block: global [ci][co][k] -> smem [ci][k][co] ----
    for (int i = tid; i < 13824; i += THREADS) {
        int ci = i / 432;
        int r  = i - ci * 432;
        int co = r / 27;
        int k  = r - co * 27;
        Ws[ci * 432 + k * 16 + co] = W[i];
    }
    float bsum = 0.f;
    #pragma unroll
    for (int i = 0; i < 16; i++) bsum += b[i];

    const int warp = tid >> 5;       // 0..15
    const int lane = tid & 31;
    const int quad = warp >> 2;      // 0..3 : cell-quad within group of 16
    const int role = (warp >> 1) & 1;// 0 = {7,3,1} (14 units), 1 = {6,5,4,2,0} (13)
    const int half = warp & 1;       // co-half: co 8*half .. 8*half+7

    // lane -> position within a 3x3x3 parity class (lanes 27..31 dup q=26)
    const int q  = (lane < 27) ? lane : 26;
    const int a  = q / 9;
    const int bq = (q - a * 9) / 3;
    const int c  = q - a * 9 - bq * 3;

    const float4* xq = xs4 + quad * 2048;

    // staging decomposition of tid
    const int s_ci = tid >> 4;
    const int s_d  = (tid >> 2) & 3;
    const int s_h  = tid & 3;

    while (true) {
        __syncthreads();            // previous iteration fully consumed
        if (tid == 0) *ctr_bc = atomicAdd(&g_ctr, 1u);
        __syncthreads();
        const unsigned g = *ctr_bc;
        if (g >= NG16) break;

        // ---- per-cell gmem base offsets ----
        if (tid < 16) {
            const int cell = g * 16 + tid;
            const int n  = cell / 1000;
            const int r3 = cell - n * 1000;
            const int pz = r3 / 100;
            const int py = (r3 / 10) % 10;
            const int px = r3 % 10;
            cb[tid] = n * 32 * 32768 + 3 * pz * 1024 + 3 * py * 32 + 3 * px;
        }
        __syncthreads();

        // ---- Stage 4 quads; thread handles (ci, d, h) for all 4 cells of a quad ----
        #pragma unroll 1
        for (int qq = 0; qq < 4; qq++) {
            float v[4][4];
            #pragma unroll
            for (int cc = 0; cc < 4; cc++) {
                const float* src = x + cb[qq * 4 + cc] + s_ci * 32768 + s_d * 1024 + s_h * 32;
                v[cc][0] = src[0]; v[cc][1] = src[1]; v[cc][2] = src[2]; v[cc][3] = src[3];
            }
            float4* dst = xs4 + qq * 2048 + s_ci * 64 + s_d * 16 + s_h * 4;
            #pragma unroll
            for (int w = 0; w < 4; w++) {
                float4 o;
                o.x = v[0][w]; o.y = v[1][w]; o.z = v[2][w]; o.w = v[3][w];
                dst[w] = o;
            }
        }
        __syncthreads();

        // ---- Compute: warp = (quad, role, half); 4 cells, 8 co ----
        float cmax[4][8];
        #pragma unroll
        for (int cc = 0; cc < 4; cc++)
            #pragma unroll
            for (int i = 0; i < 8; i++) cmax[cc][i] = -3.402823466e38f;

        const int ncls = role ? 5 : 3;
        #pragma unroll 1
        for (int ic = 0; ic < ncls; ic++) {
            int cls;
            if (role) { const int lb[5] = {6, 5, 4, 2, 0}; cls = lb[ic]; }
            else      { const int la[3] = {7, 3, 1};       cls = la[ic]; }
            const int pd = (cls >> 2) & 1;
            const int ph = (cls >> 1) & 1;
            const int pw = cls & 1;

            unsigned long long acc[4][4];
            #pragma unroll
            for (int cc = 0; cc < 4; cc++)
                #pragma unroll
                for (int i = 0; i < 4; i++) acc[cc][i] = 0ull;

            const int nd = pd + 1, nh = ph + 1, nw = pw + 1;
            #pragma unroll 1
            for (int td = 0; td < nd; td++) {
                const int kd = pd ? (2 * td)     : 1;
                const int rd = pd ? (a + 1 - td) : a;
                #pragma unroll 1
                for (int th2 = 0; th2 < nh; th2++) {
                    const int kh = ph ? (2 * th2)      : 1;
                    const int rh = ph ? (bq + 1 - th2) : bq;
                    #pragma unroll 1
                    for (int tw2 = 0; tw2 < nw; tw2++) {
                        const int kw = pw ? (2 * tw2)   : 1;
                        const int rw = pw ? (c + 1 - tw2) : c;
                        const int k  = (kd * 3 + kh) * 3 + kw;
                        const int xoff = rd * 16 + rh * 4 + rw;
                        const float4* xp = xq + xoff;
                        const ulonglong2* wp =
                            reinterpret_cast<const ulonglong2*>(Ws) + k * 4 + half * 2;
                        #pragma unroll 4
                        for (int ci = 0; ci < 32; ci++) {
                            float4 xv = xp[ci * 64];
                            unsigned long long xx0 = pack2(xv.x);
                            unsigned long long xx1 = pack2(xv.y);
                            unsigned long long xx2 = pack2(xv.z);
                            unsigned long long xx3 = pack2(xv.w);
                            ulonglong2 wA = wp[ci * 108 + 0];
                            ulonglong2 wB = wp[ci * 108 + 1];
                            fma2(acc[0][0], xx0, wA.x); fma2(acc[0][1], xx0, wA.y);
                            fma2(acc[0][2], xx0, wB.x); fma2(acc[0][3], xx0, wB.y);
                            fma2(acc[1][0], xx1, wA.x); fma2(acc[1][1], xx1, wA.y);
                            fma2(acc[1][2], xx1, wB.x); fma2(acc[1][3], xx1, wB.y);
                            fma2(acc[2][0], xx2, wA.x); fma2(acc[2][1], xx2, wA.y);
                            fma2(acc[2][2], xx2, wB.x); fma2(acc[2][3], xx2, wB.y);
                            fma2(acc[3][0], xx3, wA.x); fma2(acc[3][1], xx3, wA.y);
                            fma2(acc[3][2], xx3, wB.x); fma2(acc[3][3], xx3, wB.y);
                        }
                    }
                }
            }
            #pragma unroll
            for (int cc = 0; cc < 4; cc++)
                #pragma unroll
                for (int i = 0; i < 4; i++) {
                    float lo, hi;
                    unpack2(acc[cc][i], lo, hi);
                    cmax[cc][2 * i]     = fmaxf(cmax[cc][2 * i], lo);
                    cmax[cc][2 * i + 1] = fmaxf(cmax[cc][2 * i + 1], hi);
                }
        }

        // ---- per-warp butterfly max over positions ----
        #pragma unroll
        for (int cc = 0; cc < 4; cc++)
            #pragma unroll
            for (int i = 0; i < 8; i++) {
                #pragma unroll
                for (int off = 16; off; off >>= 1)
                    cmax[cc][i] = fmaxf(cmax[cc][i],
                                        __shfl_xor_sync(0xffffffffu, cmax[cc][i], off));
            }
        if (lane == 0) {
            #pragma unroll
            for (int cc = 0; cc < 4; cc++)
                #pragma unroll
                for (int i = 0; i < 8; i++)
                    red[warp * 32 + cc * 8 + i] = cmax[cc][i];
        }
        __syncthreads();

        // ---- combine roles per (cell, co), sum over co, write out ----
        if (tid < 16) {
            const int qd = tid >> 2;      // quad
            const int cc = tid & 3;       // cell within quad
            float t = 0.f;
            #pragma unroll
            for (int hf = 0; hf < 2; hf++)
                #pragma unroll
                for (int i = 0; i < 8; i++) {
                    const float vA = red[(qd * 4 + 0 * 2 + hf) * 32 + cc * 8 + i];
                    const float vB = red[(qd * 4 + 1 * 2 + hf) * 32 + cc * 8 + i];
                    t += fmaxf(vA, vB);
                }
            out[g * 16 + tid] = t + bsum;
        }
    }
}

extern "C" void kernel_launch(void* const* d_in, const int* in_sizes, int n_in,
                              void* d_out, int out_size)
{
    const float* x = (const float*)d_in[0];
    const float* W = (const float*)d_in[1];
    const float* b = (const float*)d_in[2];
    float* out = (float*)d_out;

    void* ctr_addr = nullptr;
    cudaGetSymbolAddress(&ctr_addr, g_ctr);
    cudaMemsetAsync(ctr_addr, 0, sizeof(unsigned));

    cudaFuncSetAttribute(fused_ct3d_pool_kernel,
                         cudaFuncAttributeMaxDynamicSharedMemorySize, SMEM_BYTES);
    fused_ct3d_pool_kernel<<<GRID_BLKS, THREADS, SMEM_BYTES>>>(x, W, b, out);
}